// round 7
// baseline (speedup 1.0000x reference)
#include <cuda_runtime.h>
#include <math.h>

#define LV 128
#define BV 32
#define TV 64
#define TDV 63
#define EV 512
#define HV 512
#define H3V 1536
#define AV 512
#define VOC 32000
#define MROWS (BV*TDV)
#define BH (BV*HV)

// ---------------- static device scratch (no dynamic alloc allowed) ----------
__device__ float g_emb[LV*BV*EV];
__device__ float g_gi0[2*LV*BV*H3V];
__device__ float g_y0[LV*BV*2*HV];
__device__ float g_gi1[2*LV*BV*H3V];
__device__ float g_y1[LV*BV*2*HV];
__device__ float g_encbt[BV*LV*HV];
__device__ float g_qenc[BV*LV*AV];
__device__ float g_demb[MROWS*EV];
__device__ float g_dgi[MROWS*H3V];
__device__ float g_feat[MROWS*2*HV];
__device__ float g_hid[MROWS*2*HV];
// recurrent states packed contiguously so one kernel zeros them all:
// [hE0 (4*BH)] [hE1 (4*BH)] [hd0 (2*BH)] [hd1 (2*BH)] [ctx (BH)]
__device__ float g_state[13*BH];

typedef unsigned long long u64;

__device__ __forceinline__ u64 splat2(float x) {
    u64 r; asm("mov.b64 %0, {%1, %1};" : "=l"(r) : "f"(x)); return r;
}
__device__ __forceinline__ void fma2(u64& d, u64 a, u64 b) {
    asm("fma.rn.f32x2 %0, %1, %2, %0;" : "+l"(d) : "l"(a), "l"(b));
}
__device__ __forceinline__ float2 up2(u64 v) {
    float2 f; asm("mov.b64 {%0, %1}, %2;" : "=f"(f.x), "=f"(f.y) : "l"(v)); return f;
}
__device__ __forceinline__ float hsum2(u64 v) {
    float2 f = up2(v); return f.x + f.y;
}

// ---------------- zero helper ----------------------------------------------
__global__ void zero_f(float* p, int n) {
    int i = blockIdx.x * 256 + threadIdx.x;
    if (i < n) p[i] = 0.f;
}

// ---------------- embedding gathers ----------------------------------------
__global__ void gather_src(const float* __restrict__ tab, const int* __restrict__ tok,
                           float* __restrict__ out) {
    int row = blockIdx.x;               // l*B + b
    int tk = tok[row];
    const float4* s = (const float4*)(tab + (size_t)tk * EV);
    float4* d = (float4*)(out + (size_t)row * EV);
    d[threadIdx.x] = s[threadIdx.x];    // 128 threads * 4 floats
}
__global__ void gather_dec(const float* __restrict__ tab, const int* __restrict__ tok,
                           float* __restrict__ out) {
    int row = blockIdx.x;               // t*32 + b
    int t = row >> 5, b = row & 31;
    int tk = tok[b * TV + t];
    const float4* s = (const float4*)(tab + (size_t)tk * EV);
    float4* d = (float4*)(out + (size_t)row * EV);
    d[threadIdx.x] = s[threadIdx.x];
}

// ---------------- SGEMM: C[M,N] = A[M,K] * W[N,K]^T + bias ------------------
// 128x128 tile, BK=8, 256 threads, split 2x(4x4)x2 microtile, f32x2 FMA.
// Rows per thread: {my*4..+3, 64+my*4..+3}; cols: {tx*4..+3, 64+tx*4..+3}.
// All smem loads are conflict-free LDS.128 (B: 256B contiguous per warp-half;
// A: 16-way broadcast). A staged pre-splatted as u64 pairs.
// N multiple of 128; M guarded.
__global__ __launch_bounds__(256, 2) void sgemm_tn(
    const float* __restrict__ A, int lda,
    const float* __restrict__ W, int ldw,
    const float* __restrict__ bias,
    float* __restrict__ C, int ldc,
    int M, int K, int relu)
{
    __shared__ __align__(16) u64   As2[8][128];
    __shared__ __align__(16) float Bs[8][128];
    int tid = threadIdx.x;
    int mt = blockIdx.x, nt = blockIdx.y;
    int lr = tid >> 1, lc = (tid & 1) << 2;
    int am = mt * 128 + lr; if (am >= M) am = M - 1;
    const float* aptr = A + (size_t)am * lda + lc;
    const float* wptr = W + (size_t)(nt * 128 + lr) * ldw + lc;
    int my = tid >> 4, tx = tid & 15;

    u64 acc[8][4];
#pragma unroll
    for (int i = 0; i < 8; i++) { acc[i][0] = 0; acc[i][1] = 0; acc[i][2] = 0; acc[i][3] = 0; }

    float4 a4 = *(const float4*)aptr;
    float4 w4 = *(const float4*)wptr;
    for (int k0 = 0; k0 < K; k0 += 8) {
        __syncthreads();
        As2[lc + 0][lr] = splat2(a4.x); As2[lc + 1][lr] = splat2(a4.y);
        As2[lc + 2][lr] = splat2(a4.z); As2[lc + 3][lr] = splat2(a4.w);
        Bs[lc + 0][lr] = w4.x; Bs[lc + 1][lr] = w4.y; Bs[lc + 2][lr] = w4.z; Bs[lc + 3][lr] = w4.w;
        __syncthreads();
        if (k0 + 8 < K) {
            a4 = *(const float4*)(aptr + k0 + 8);
            w4 = *(const float4*)(wptr + k0 + 8);
        }
#pragma unroll
        for (int k = 0; k < 8; k++) {
            float4 bv0 = *(const float4*)&Bs[k][tx * 4];        // cols tx*4..+3
            float4 bv1 = *(const float4*)&Bs[k][64 + tx * 4];   // cols 64+tx*4..+3
            u64 b00 = ((const u64*)&bv0)[0], b01 = ((const u64*)&bv0)[1];
            u64 b10 = ((const u64*)&bv1)[0], b11 = ((const u64*)&bv1)[1];
            ulonglong2 a01 = *(const ulonglong2*)&As2[k][my * 4];
            ulonglong2 a23 = *(const ulonglong2*)&As2[k][my * 4 + 2];
            ulonglong2 a45 = *(const ulonglong2*)&As2[k][64 + my * 4];
            ulonglong2 a67 = *(const ulonglong2*)&As2[k][64 + my * 4 + 2];
            u64 av[8] = {a01.x, a01.y, a23.x, a23.y, a45.x, a45.y, a67.x, a67.y};
#pragma unroll
            for (int mi = 0; mi < 8; mi++) {
                fma2(acc[mi][0], av[mi], b00);
                fma2(acc[mi][1], av[mi], b01);
                fma2(acc[mi][2], av[mi], b10);
                fma2(acc[mi][3], av[mi], b11);
            }
        }
    }
    int nn0 = nt * 128 + tx * 4;
    int nn1 = nt * 128 + 64 + tx * 4;
    float4 bb0 = *(const float4*)(bias + nn0);
    float4 bb1 = *(const float4*)(bias + nn1);
#pragma unroll
    for (int mi = 0; mi < 8; mi++) {
        int m = mt * 128 + ((mi < 4) ? (my * 4 + mi) : (64 + my * 4 + (mi - 4)));
        if (m < M) {
            float2 p0 = up2(acc[mi][0]), p1 = up2(acc[mi][1]);
            float2 p2 = up2(acc[mi][2]), p3 = up2(acc[mi][3]);
            float4 o0 = make_float4(p0.x + bb0.x, p0.y + bb0.y, p1.x + bb0.z, p1.y + bb0.w);
            float4 o1 = make_float4(p2.x + bb1.x, p2.y + bb1.y, p3.x + bb1.z, p3.y + bb1.w);
            if (relu) {
                o0.x = fmaxf(o0.x, 0.f); o0.y = fmaxf(o0.y, 0.f);
                o0.z = fmaxf(o0.z, 0.f); o0.w = fmaxf(o0.w, 0.f);
                o1.x = fmaxf(o1.x, 0.f); o1.y = fmaxf(o1.y, 0.f);
                o1.z = fmaxf(o1.z, 0.f); o1.w = fmaxf(o1.w, 0.f);
            }
            *(float4*)(C + (size_t)m * ldc + nn0) = o0;
            *(float4*)(C + (size_t)m * ldc + nn1) = o1;
        }
    }
}

// ---------------- encoder GRU step (both directions, packed-K f32x2) --------
// grid (64, 2), 256 threads: warp -> output column (8 cols/block), lane -> batch.
__global__ __launch_bounds__(256) void gru_step_enc(
    const float* __restrict__ giF, const float* __restrict__ giB,
    const float* __restrict__ Whh, const float* __restrict__ bhh,
    float* __restrict__ hE, int ping,
    float* __restrict__ y, int tf, int tb)
{
    int dir = blockIdx.y;
    const float* gi = dir ? giB : giF;
    int trow = dir ? tb : tf;
    const float* hin = hE + dir * 2 * BH + ping * BH;
    float* hout = hE + dir * 2 * BH + (ping ^ 1) * BH;
    const float* W = Whh + (size_t)dir * H3V * HV;
    const float* bh = bhh + dir * H3V;

    __shared__ u64 hP[64][33];   // [k-pair][batch], padded
    int tid = threadIdx.x, lane = tid & 31, warp = tid >> 5;
    int c = blockIdx.x * 8 + warp;
    u64 aR = 0, aZ = 0, aN = 0;
    const float* wR = W + (size_t)c * HV;
    const float* wZ = W + (size_t)(c + 512) * HV;
    const float* wN = W + (size_t)(c + 1024) * HV;
    const float2* hin2 = (const float2*)hin;

    for (int k0 = 0; k0 < HV; k0 += 128) {
        __syncthreads();
#pragma unroll
        for (int i = tid; i < 2048; i += 256) {
            int kp = i & 63, bb = i >> 6;
            float2 v = hin2[bb * 256 + (k0 >> 1) + kp];
            hP[kp][bb] = *(const u64*)&v;
        }
        __syncthreads();
#pragma unroll 8
        for (int kp = 0; kp < 64; kp += 2) {
            float4 r4 = *(const float4*)(wR + k0 + 2 * kp);
            float4 z4 = *(const float4*)(wZ + k0 + 2 * kp);
            float4 n4 = *(const float4*)(wN + k0 + 2 * kp);
            u64 h0 = hP[kp][lane], h1 = hP[kp + 1][lane];
            const u64* rp = (const u64*)&r4;
            const u64* zp = (const u64*)&z4;
            const u64* np = (const u64*)&n4;
            fma2(aR, h0, rp[0]); fma2(aR, h1, rp[1]);
            fma2(aZ, h0, zp[0]); fma2(aZ, h1, zp[1]);
            fma2(aN, h0, np[0]); fma2(aN, h1, np[1]);
        }
    }
    int b = lane;
    size_t gbase = (size_t)(trow * BV + b) * H3V + c;
    float ir = gi[gbase], iz = gi[gbase + 512], inn = gi[gbase + 1024];
    float hr = hsum2(aR) + bh[c], hz = hsum2(aZ) + bh[c + 512], hn = hsum2(aN) + bh[c + 1024];
    float r = 1.f / (1.f + expf(-(ir + hr)));
    float z = 1.f / (1.f + expf(-(iz + hz)));
    float n = tanhf(inn + r * hn);
    float hp = hin[b * HV + c];
    float hnew = (1.f - z) * n + z * hp;
    hout[b * HV + c] = hnew;
    y[(size_t)(trow * BV + b) * (2 * HV) + dir * HV + c] = hnew;
}

// ---------------- decoder GRU step (generic, packed-K f32x2) -----------------
// grid 128 blocks x 128 threads: warp -> column (4 cols/block), lane -> batch.
// gi_gate = gib[b*gibs + row] + x[b].Wx[row];  gh_gate = h[b].Whh[row] + bhh[row]
__global__ __launch_bounds__(128) void gru_step_dec(
    const float* __restrict__ gib, int gibs,
    const float* __restrict__ x, const float* __restrict__ Wx, int ldwx,
    const float* __restrict__ hin, const float* __restrict__ Whh,
    const float* __restrict__ bhh, float* __restrict__ hout)
{
    __shared__ u64 xP[64][33];
    __shared__ u64 hP[64][33];
    int tid = threadIdx.x, lane = tid & 31, warp = tid >> 5;
    int c = blockIdx.x * 4 + warp;
    u64 xR = 0, xZ = 0, xN = 0, hR = 0, hZ = 0, hN = 0;
    const float* wxR = Wx + (size_t)c * ldwx;
    const float* wxZ = Wx + (size_t)(c + 512) * ldwx;
    const float* wxN = Wx + (size_t)(c + 1024) * ldwx;
    const float* whR = Whh + (size_t)c * HV;
    const float* whZ = Whh + (size_t)(c + 512) * HV;
    const float* whN = Whh + (size_t)(c + 1024) * HV;
    const float2* x2 = (const float2*)x;
    const float2* h2 = (const float2*)hin;

    for (int k0 = 0; k0 < HV; k0 += 128) {
        __syncthreads();
#pragma unroll
        for (int i = tid; i < 2048; i += 128) {
            int kp = i & 63, bb = i >> 6;
            float2 xv = x2[bb * 256 + (k0 >> 1) + kp];
            float2 hv = h2[bb * 256 + (k0 >> 1) + kp];
            xP[kp][bb] = *(const u64*)&xv;
            hP[kp][bb] = *(const u64*)&hv;
        }
        __syncthreads();
#pragma unroll 4
        for (int kp = 0; kp < 64; kp += 2) {
            float4 a4 = *(const float4*)(wxR + k0 + 2 * kp);
            float4 b4 = *(const float4*)(wxZ + k0 + 2 * kp);
            float4 c4 = *(const float4*)(wxN + k0 + 2 * kp);
            float4 d4 = *(const float4*)(whR + k0 + 2 * kp);
            float4 e4 = *(const float4*)(whZ + k0 + 2 * kp);
            float4 f4 = *(const float4*)(whN + k0 + 2 * kp);
            u64 xv0 = xP[kp][lane], xv1 = xP[kp + 1][lane];
            u64 hv0 = hP[kp][lane], hv1 = hP[kp + 1][lane];
            fma2(xR, xv0, ((const u64*)&a4)[0]); fma2(xR, xv1, ((const u64*)&a4)[1]);
            fma2(xZ, xv0, ((const u64*)&b4)[0]); fma2(xZ, xv1, ((const u64*)&b4)[1]);
            fma2(xN, xv0, ((const u64*)&c4)[0]); fma2(xN, xv1, ((const u64*)&c4)[1]);
            fma2(hR, hv0, ((const u64*)&d4)[0]); fma2(hR, hv1, ((const u64*)&d4)[1]);
            fma2(hZ, hv0, ((const u64*)&e4)[0]); fma2(hZ, hv1, ((const u64*)&e4)[1]);
            fma2(hN, hv0, ((const u64*)&f4)[0]); fma2(hN, hv1, ((const u64*)&f4)[1]);
        }
    }
    int b = lane;
    float ir = gib[(size_t)b * gibs + c] + hsum2(xR);
    float iz = gib[(size_t)b * gibs + c + 512] + hsum2(xZ);
    float inn = gib[(size_t)b * gibs + c + 1024] + hsum2(xN);
    float hr = hsum2(hR) + bhh[c], hz = hsum2(hZ) + bhh[c + 512], hn = hsum2(hN) + bhh[c + 1024];
    float r = 1.f / (1.f + expf(-(ir + hr)));
    float z = 1.f / (1.f + expf(-(iz + hz)));
    float n = tanhf(inn + r * hn);
    float hp = hin[b * HV + c];
    hout[b * HV + c] = (1.f - z) * n + z * hp;
}

// ---------------- attention step: q proj + scores + softmax + context -------
__global__ __launch_bounds__(256) void attn_step(
    const float* __restrict__ h1n, const float* __restrict__ qenc,
    const float* __restrict__ encbt, const float* __restrict__ Wd,
    const float* __restrict__ bd, float* __restrict__ ctx,
    float* __restrict__ feat, int t)
{
    int b = blockIdx.x;
    __shared__ float h1s[512], qs[512], es[128], red1[8], red2[8];
    int tid = threadIdx.x, lane = tid & 31, warp = tid >> 5;
    h1s[tid] = h1n[b * 512 + tid];
    h1s[tid + 256] = h1n[b * 512 + tid + 256];
    __syncthreads();
    // q[a] = h1n[b] . Wd[a] + bd[a]
    for (int ai = 0; ai < 64; ai++) {
        int a = warp * 64 + ai;
        const float* w = Wd + (size_t)a * 512;
        float s = 0.f;
#pragma unroll
        for (int i = 0; i < 16; i++) s += h1s[lane + 32 * i] * w[lane + 32 * i];
#pragma unroll
        for (int o = 16; o; o >>= 1) s += __shfl_xor_sync(0xffffffffu, s, o);
        if (lane == 0) qs[a] = s + bd[a];
    }
    __syncthreads();
    // e[l] = tanh(enc_q[b][l] . q)
    for (int li = 0; li < 16; li++) {
        int l = warp * 16 + li;
        const float* eq = qenc + (size_t)(b * LV + l) * AV;
        float s = 0.f;
#pragma unroll
        for (int i = 0; i < 16; i++) s += qs[lane + 32 * i] * eq[lane + 32 * i];
#pragma unroll
        for (int o = 16; o; o >>= 1) s += __shfl_xor_sync(0xffffffffu, s, o);
        if (lane == 0) es[l] = tanhf(s);
    }
    __syncthreads();
    // softmax over 128
    float v = (tid < 128) ? es[tid] : -1e30f;
    float m = v;
#pragma unroll
    for (int o = 16; o; o >>= 1) m = fmaxf(m, __shfl_xor_sync(0xffffffffu, m, o));
    if (lane == 0) red1[warp] = m;
    __syncthreads();
    float mx = fmaxf(fmaxf(fmaxf(red1[0], red1[1]), fmaxf(red1[2], red1[3])),
                     fmaxf(fmaxf(red1[4], red1[5]), fmaxf(red1[6], red1[7])));
    float ex = (tid < 128) ? expf(v - mx) : 0.f;
    float s2 = ex;
#pragma unroll
    for (int o = 16; o; o >>= 1) s2 += __shfl_xor_sync(0xffffffffu, s2, o);
    if (lane == 0) red2[warp] = s2;
    __syncthreads();
    float tot = red2[0] + red2[1] + red2[2] + red2[3] + red2[4] + red2[5] + red2[6] + red2[7];
    if (tid < 128) es[tid] = ex / tot;
    __syncthreads();
    // ctx2[h] = sum_l w[l] * enc_bt[b][l][h]
    float c0 = 0.f, c1 = 0.f;
    for (int l = 0; l < 128; l++) {
        float w = es[l];
        const float* er = encbt + (size_t)(b * LV + l) * HV;
        c0 += w * er[tid];
        c1 += w * er[tid + 256];
    }
    ctx[b * HV + tid] = c0;
    ctx[b * HV + tid + 256] = c1;
    float* fr = feat + (size_t)(b * TDV + t) * 1024;
    fr[tid] = h1s[tid];
    fr[tid + 256] = h1s[tid + 256];
    fr[512 + tid] = c0;
    fr[512 + tid + 256] = c1;
}

// ---------------- encoder output: sum halves + transpose --------------------
__global__ void enc_combine(const float* __restrict__ y1, float* __restrict__ encbt) {
    int i = blockIdx.x * 256 + threadIdx.x;
    if (i >= BV * LV * HV) return;
    int h = i & 511; int bl = i >> 9; int b = bl >> 7; int l = bl & 127;
    size_t src = (size_t)(l * BV + b) * 1024 + h;
    encbt[i] = y1[src] + y1[src + 512];
}

// ---------------- host orchestration ----------------------------------------
extern "C" void kernel_launch(void* const* d_in, const int* in_sizes, int n_in,
                              void* d_out, int out_size) {
    const int* src = (const int*)d_in[0];
    const int* trg = (const int*)d_in[1];
    int o = (n_in >= 29 && in_sizes[2] == 1) ? 3 : 2;   // skip out_len scalar if present
    const float* enc_embed = (const float*)d_in[o + 0];
    const float* eWih0 = (const float*)d_in[o + 1];
    const float* eWhh0 = (const float*)d_in[o + 2];
    const float* ebih0 = (const float*)d_in[o + 3];
    const float* ebhh0 = (const float*)d_in[o + 4];
    const float* eWih1 = (const float*)d_in[o + 5];
    const float* eWhh1 = (const float*)d_in[o + 6];
    const float* ebih1 = (const float*)d_in[o + 7];
    const float* ebhh1 = (const float*)d_in[o + 8];
    const float* dec_embed = (const float*)d_in[o + 9];
    const float* dWih0 = (const float*)d_in[o + 10];
    const float* dWhh0 = (const float*)d_in[o + 11];
    const float* dbih0 = (const float*)d_in[o + 12];
    const float* dbhh0 = (const float*)d_in[o + 13];
    const float* dWih1 = (const float*)d_in[o + 14];
    const float* dWhh1 = (const float*)d_in[o + 15];
    const float* dbih1 = (const float*)d_in[o + 16];
    const float* dbhh1 = (const float*)d_in[o + 17];
    const float* We = (const float*)d_in[o + 18];
    const float* be = (const float*)d_in[o + 19];
    const float* Wd = (const float*)d_in[o + 20];
    const float* bd = (const float*)d_in[o + 21];
    const float* W1 = (const float*)d_in[o + 22];
    const float* b1 = (const float*)d_in[o + 23];
    const float* W2 = (const float*)d_in[o + 24];
    const float* b2 = (const float*)d_in[o + 25];
    float* out = (float*)d_out;

    float *emb, *gi0, *y0, *gi1, *y1, *encbt, *qenc, *demb, *dgi, *feat, *hid, *st;
    cudaGetSymbolAddress((void**)&emb, g_emb);
    cudaGetSymbolAddress((void**)&gi0, g_gi0);
    cudaGetSymbolAddress((void**)&y0, g_y0);
    cudaGetSymbolAddress((void**)&gi1, g_gi1);
    cudaGetSymbolAddress((void**)&y1, g_y1);
    cudaGetSymbolAddress((void**)&encbt, g_encbt);
    cudaGetSymbolAddress((void**)&qenc, g_qenc);
    cudaGetSymbolAddress((void**)&demb, g_demb);
    cudaGetSymbolAddress((void**)&dgi, g_dgi);
    cudaGetSymbolAddress((void**)&feat, g_feat);
    cudaGetSymbolAddress((void**)&hid, g_hid);
    cudaGetSymbolAddress((void**)&st, g_state);
    float* hE0 = st;                 // 4*BH
    float* hE1 = st + 4 * BH;        // 4*BH
    float* hd0 = st + 8 * BH;        // 2*BH
    float* hd1 = st + 10 * BH;       // 2*BH
    float* ctx = st + 12 * BH;       // BH

    // zero ALL recurrent state in one launch (deterministic every call)
    zero_f<<<(13 * BH + 255) / 256, 256>>>(st, 13 * BH);

    // ---------------- encoder ----------------
    gather_src<<<LV * BV, 128>>>(enc_embed, src, emb);
    for (int d = 0; d < 2; d++)
        sgemm_tn<<<dim3(32, 12), 256>>>(emb, 512, eWih0 + (size_t)d * H3V * EV, 512,
                                        ebih0 + d * H3V, gi0 + (size_t)d * LV * BV * H3V, H3V,
                                        LV * BV, 512, 0);
    for (int t = 0; t < LV; t++)
        gru_step_enc<<<dim3(64, 2), 256>>>(gi0, gi0 + (size_t)LV * BV * H3V,
                                           eWhh0, ebhh0, hE0, t & 1, y0, t, LV - 1 - t);
    for (int d = 0; d < 2; d++)
        sgemm_tn<<<dim3(32, 12), 256>>>(y0, 1024, eWih1 + (size_t)d * H3V * 1024, 1024,
                                        ebih1 + d * H3V, gi1 + (size_t)d * LV * BV * H3V, H3V,
                                        LV * BV, 1024, 0);
    for (int t = 0; t < LV; t++)
        gru_step_enc<<<dim3(64, 2), 256>>>(gi1, gi1 + (size_t)LV * BV * H3V,
                                           eWhh1, ebhh1, hE1, t & 1, y1, t, LV - 1 - t);
    enc_combine<<<(BV * LV * HV + 255) / 256, 256>>>(y1, encbt);
    sgemm_tn<<<dim3(32, 4), 256>>>(encbt, 512, We, 512, be, qenc, 512, BV * LV, 512, 0);

    // ---------------- decoder precompute ----------------
    gather_dec<<<MROWS, 128>>>(dec_embed, trg, demb);
    sgemm_tn<<<dim3(16, 12), 256>>>(demb, 512, dWih0, 1024, dbih0, dgi, H3V, MROWS, 512, 0);

    // ---------------- decode loop ----------------
    for (int t = 0; t < TDV; t++) {
        int ping = t & 1, pong = ping ^ 1;
        gru_step_dec<<<128, 128>>>(dgi + (size_t)t * BV * H3V, H3V, ctx, dWih0 + 512, 1024,
                                   hd0 + ping * BH, dWhh0, dbhh0, hd0 + pong * BH);
        gru_step_dec<<<128, 128>>>(dbih1, 0, hd0 + pong * BH, dWih1, 512,
                                   hd1 + ping * BH, dWhh1, dbhh1, hd1 + pong * BH);
        attn_step<<<BV, 256>>>(hd1 + pong * BH, qenc, encbt, Wd, bd, ctx, feat, t);
    }

    // ---------------- MLP + logits ----------------
    sgemm_tn<<<dim3(16, 8), 256>>>(feat, 1024, W1, 1024, b1, hid, 1024, MROWS, 1024, 1);
    sgemm_tn<<<dim3(16, 250), 256>>>(hid, 1024, W2, 1024, b2, out, VOC, MROWS, 1024, 0);
}

// round 8
// speedup vs baseline: 1.3478x; 1.3478x over previous
#include <cuda_runtime.h>
#include <math.h>

#define LV 128
#define BV 32
#define TV 64
#define TDV 63
#define EV 512
#define HV 512
#define H3V 1536
#define AV 512
#define VOC 32000
#define MROWS (BV*TDV)
#define BH (BV*HV)

// ---------------- static device scratch (no dynamic alloc allowed) ----------
__device__ float g_emb[LV*BV*EV];
__device__ float g_gi0[2*LV*BV*H3V];
__device__ float g_y0[LV*BV*2*HV];
__device__ float g_gi1[2*LV*BV*H3V];
__device__ float g_y1[LV*BV*2*HV];
__device__ float g_encbt[BV*LV*HV];
__device__ float g_qenc[BV*LV*AV];
__device__ float g_demb[MROWS*EV];
__device__ float g_dgi[MROWS*H3V];
__device__ float g_feat[MROWS*2*HV];
__device__ float g_hid[MROWS*2*HV];
// recurrent states packed contiguously so one kernel zeros them all:
// [hE0 (4*BH)] [hE1 (4*BH)] [hd0 (2*BH)] [hd1 (2*BH)] [ctx (BH)]
__device__ float g_state[13*BH];

typedef unsigned long long u64;

__device__ __forceinline__ u64 splat2(float x) {
    u64 r; asm("mov.b64 %0, {%1, %1};" : "=l"(r) : "f"(x)); return r;
}
__device__ __forceinline__ void fma2(u64& d, u64 a, u64 b) {
    asm("fma.rn.f32x2 %0, %1, %2, %0;" : "+l"(d) : "l"(a), "l"(b));
}
__device__ __forceinline__ float2 up2(u64 v) {
    float2 f; asm("mov.b64 {%0, %1}, %2;" : "=f"(f.x), "=f"(f.y) : "l"(v)); return f;
}
__device__ __forceinline__ float hsum2(u64 v) {
    float2 f = up2(v); return f.x + f.y;
}

// ---------------- zero helper ----------------------------------------------
__global__ void zero_f(float* p, int n) {
    int i = blockIdx.x * 256 + threadIdx.x;
    if (i < n) p[i] = 0.f;
}

// ---------------- embedding gathers ----------------------------------------
__global__ void gather_src(const float* __restrict__ tab, const int* __restrict__ tok,
                           float* __restrict__ out) {
    int row = blockIdx.x;               // l*B + b
    int tk = tok[row];
    const float4* s = (const float4*)(tab + (size_t)tk * EV);
    float4* d = (float4*)(out + (size_t)row * EV);
    d[threadIdx.x] = s[threadIdx.x];    // 128 threads * 4 floats
}
__global__ void gather_dec(const float* __restrict__ tab, const int* __restrict__ tok,
                           float* __restrict__ out) {
    int row = blockIdx.x;               // t*32 + b
    int t = row >> 5, b = row & 31;
    int tk = tok[b * TV + t];
    const float4* s = (const float4*)(tab + (size_t)tk * EV);
    float4* d = (float4*)(out + (size_t)row * EV);
    d[threadIdx.x] = s[threadIdx.x];
}

// ---------------- SGEMM: C[M,N] = A[M,K] * W[N,K]^T + bias ------------------
// 128x128 tile, BK=8, 256 threads, split 2x(4x4)x2 microtile, f32x2 FMA.
// Double-buffered smem: ONE __syncthreads per k-tile; global prefetch issued
// before compute. All smem loads conflict-free LDS.128.
__global__ __launch_bounds__(256, 2) void sgemm_tn(
    const float* __restrict__ A, int lda,
    const float* __restrict__ W, int ldw,
    const float* __restrict__ bias,
    float* __restrict__ C, int ldc,
    int M, int K, int relu)
{
    __shared__ __align__(16) u64   As2[2][8][128];
    __shared__ __align__(16) float Bs[2][8][128];
    int tid = threadIdx.x;
    int mt = blockIdx.x, nt = blockIdx.y;
    int lr = tid >> 1, lc = (tid & 1) << 2;
    int am = mt * 128 + lr; if (am >= M) am = M - 1;
    const float* aptr = A + (size_t)am * lda + lc;
    const float* wptr = W + (size_t)(nt * 128 + lr) * ldw + lc;
    int my = tid >> 4, tx = tid & 15;

    u64 acc[8][4];
#pragma unroll
    for (int i = 0; i < 8; i++) { acc[i][0] = 0; acc[i][1] = 0; acc[i][2] = 0; acc[i][3] = 0; }

    float4 a4 = *(const float4*)aptr;
    float4 w4 = *(const float4*)wptr;
    As2[0][lc + 0][lr] = splat2(a4.x); As2[0][lc + 1][lr] = splat2(a4.y);
    As2[0][lc + 2][lr] = splat2(a4.z); As2[0][lc + 3][lr] = splat2(a4.w);
    Bs[0][lc + 0][lr] = w4.x; Bs[0][lc + 1][lr] = w4.y;
    Bs[0][lc + 2][lr] = w4.z; Bs[0][lc + 3][lr] = w4.w;
    __syncthreads();

    int buf = 0;
    for (int k0 = 0; k0 < K; k0 += 8) {
        bool more = (k0 + 8 < K);
        if (more) {
            a4 = *(const float4*)(aptr + k0 + 8);
            w4 = *(const float4*)(wptr + k0 + 8);
        }
#pragma unroll
        for (int k = 0; k < 8; k++) {
            float4 bv0 = *(const float4*)&Bs[buf][k][tx * 4];
            float4 bv1 = *(const float4*)&Bs[buf][k][64 + tx * 4];
            u64 b00 = ((const u64*)&bv0)[0], b01 = ((const u64*)&bv0)[1];
            u64 b10 = ((const u64*)&bv1)[0], b11 = ((const u64*)&bv1)[1];
            ulonglong2 a01 = *(const ulonglong2*)&As2[buf][k][my * 4];
            ulonglong2 a23 = *(const ulonglong2*)&As2[buf][k][my * 4 + 2];
            ulonglong2 a45 = *(const ulonglong2*)&As2[buf][k][64 + my * 4];
            ulonglong2 a67 = *(const ulonglong2*)&As2[buf][k][64 + my * 4 + 2];
            u64 av[8] = {a01.x, a01.y, a23.x, a23.y, a45.x, a45.y, a67.x, a67.y};
#pragma unroll
            for (int mi = 0; mi < 8; mi++) {
                fma2(acc[mi][0], av[mi], b00);
                fma2(acc[mi][1], av[mi], b01);
                fma2(acc[mi][2], av[mi], b10);
                fma2(acc[mi][3], av[mi], b11);
            }
        }
        if (more) {
            int nb = buf ^ 1;
            As2[nb][lc + 0][lr] = splat2(a4.x); As2[nb][lc + 1][lr] = splat2(a4.y);
            As2[nb][lc + 2][lr] = splat2(a4.z); As2[nb][lc + 3][lr] = splat2(a4.w);
            Bs[nb][lc + 0][lr] = w4.x; Bs[nb][lc + 1][lr] = w4.y;
            Bs[nb][lc + 2][lr] = w4.z; Bs[nb][lc + 3][lr] = w4.w;
            __syncthreads();
            buf = nb;
        }
    }
    int nn0 = nt * 128 + tx * 4;
    int nn1 = nt * 128 + 64 + tx * 4;
    float4 bb0 = *(const float4*)(bias + nn0);
    float4 bb1 = *(const float4*)(bias + nn1);
#pragma unroll
    for (int mi = 0; mi < 8; mi++) {
        int m = mt * 128 + ((mi < 4) ? (my * 4 + mi) : (64 + my * 4 + (mi - 4)));
        if (m < M) {
            float2 p0 = up2(acc[mi][0]), p1 = up2(acc[mi][1]);
            float2 p2 = up2(acc[mi][2]), p3 = up2(acc[mi][3]);
            float4 o0 = make_float4(p0.x + bb0.x, p0.y + bb0.y, p1.x + bb0.z, p1.y + bb0.w);
            float4 o1 = make_float4(p2.x + bb1.x, p2.y + bb1.y, p3.x + bb1.z, p3.y + bb1.w);
            if (relu) {
                o0.x = fmaxf(o0.x, 0.f); o0.y = fmaxf(o0.y, 0.f);
                o0.z = fmaxf(o0.z, 0.f); o0.w = fmaxf(o0.w, 0.f);
                o1.x = fmaxf(o1.x, 0.f); o1.y = fmaxf(o1.y, 0.f);
                o1.z = fmaxf(o1.z, 0.f); o1.w = fmaxf(o1.w, 0.f);
            }
            *(float4*)(C + (size_t)m * ldc + nn0) = o0;
            *(float4*)(C + (size_t)m * ldc + nn1) = o1;
        }
    }
}

// ---------------- encoder GRU step (2 warps per column, K-split) ------------
// grid (128, 2), 256 threads = 8 warps = 4 cols x 2 K-halves; lane -> batch.
// Half hf processes kp pairs {4j+2hf, 4j+2hf+1} within each 64-kp chunk.
__global__ __launch_bounds__(256) void gru_step_enc(
    const float* __restrict__ giF, const float* __restrict__ giB,
    const float* __restrict__ Whh, const float* __restrict__ bhh,
    float* __restrict__ hE, int ping,
    float* __restrict__ y, int tf, int tb)
{
    int dir = blockIdx.y;
    const float* gi = dir ? giB : giF;
    int trow = dir ? tb : tf;
    const float* hin = hE + dir * 2 * BH + ping * BH;
    float* hout = hE + dir * 2 * BH + (ping ^ 1) * BH;
    const float* W = Whh + (size_t)dir * H3V * HV;
    const float* bh = bhh + dir * H3V;

    __shared__ u64 hP[64][33];       // [k-pair][batch], padded
    __shared__ u64 cmb[8][32][3];    // per-warp partials
    int tid = threadIdx.x, lane = tid & 31, w = tid >> 5;
    int cw = w >> 1, hf = w & 1;
    int c = blockIdx.x * 4 + cw;
    u64 aR = 0, aZ = 0, aN = 0;
    const float* wR = W + (size_t)c * HV;
    const float* wZ = W + (size_t)(c + 512) * HV;
    const float* wN = W + (size_t)(c + 1024) * HV;
    const float2* hin2 = (const float2*)hin;

    for (int k0 = 0; k0 < HV; k0 += 128) {
        __syncthreads();
#pragma unroll
        for (int i = tid; i < 2048; i += 256) {
            int kp = i & 63, bb = i >> 6;
            float2 v = hin2[bb * 256 + (k0 >> 1) + kp];
            hP[kp][bb] = *(const u64*)&v;
        }
        __syncthreads();
#pragma unroll
        for (int j = 0; j < 16; j++) {
            int kp0 = 4 * j + 2 * hf;
            float4 r4 = *(const float4*)(wR + k0 + 2 * kp0);
            float4 z4 = *(const float4*)(wZ + k0 + 2 * kp0);
            float4 n4 = *(const float4*)(wN + k0 + 2 * kp0);
            u64 h0 = hP[kp0][lane], h1 = hP[kp0 + 1][lane];
            fma2(aR, h0, ((const u64*)&r4)[0]); fma2(aR, h1, ((const u64*)&r4)[1]);
            fma2(aZ, h0, ((const u64*)&z4)[0]); fma2(aZ, h1, ((const u64*)&z4)[1]);
            fma2(aN, h0, ((const u64*)&n4)[0]); fma2(aN, h1, ((const u64*)&n4)[1]);
        }
    }
    cmb[w][lane][0] = aR; cmb[w][lane][1] = aZ; cmb[w][lane][2] = aN;
    __syncthreads();
    if (hf == 0) {
        int b = lane;
        float sR = hsum2(cmb[w][b][0]) + hsum2(cmb[w + 1][b][0]);
        float sZ = hsum2(cmb[w][b][1]) + hsum2(cmb[w + 1][b][1]);
        float sN = hsum2(cmb[w][b][2]) + hsum2(cmb[w + 1][b][2]);
        size_t gbase = (size_t)(trow * BV + b) * H3V + c;
        float ir = gi[gbase], iz = gi[gbase + 512], inn = gi[gbase + 1024];
        float hr = sR + bh[c], hz = sZ + bh[c + 512], hn = sN + bh[c + 1024];
        float r = 1.f / (1.f + expf(-(ir + hr)));
        float z = 1.f / (1.f + expf(-(iz + hz)));
        float n = tanhf(inn + r * hn);
        float hp = hin[b * HV + c];
        float hnew = (1.f - z) * n + z * hp;
        hout[b * HV + c] = hnew;
        y[(size_t)(trow * BV + b) * (2 * HV) + dir * HV + c] = hnew;
    }
}

// ---------------- decoder GRU step (4 warps per column) ----------------------
// 128 blocks x 512 threads = 16 warps = 4 cols x 2 sides (x/h) x 2 K-halves.
// gi_gate = gib[b*gibs + row] + x[b].Wx[row];  gh_gate = h[b].Whh[row] + bhh[row]
__global__ __launch_bounds__(512) void gru_step_dec(
    const float* __restrict__ gib, int gibs,
    const float* __restrict__ x, const float* __restrict__ Wx, int ldwx,
    const float* __restrict__ hin, const float* __restrict__ Whh,
    const float* __restrict__ bhh, float* __restrict__ hout)
{
    __shared__ u64 xP[64][33];
    __shared__ u64 hP[64][33];
    __shared__ u64 cmb[16][32][3];
    int tid = threadIdx.x, lane = tid & 31, w = tid >> 5;
    int cw = w >> 2, sd = (w >> 1) & 1, hf = w & 1;
    int c = blockIdx.x * 4 + cw;
    u64 s0 = 0, s1 = 0, s2 = 0;
    const float* Wb = sd ? Whh : Wx;
    int ld = sd ? HV : ldwx;
    const float* w0 = Wb + (size_t)c * ld;
    const float* w1 = Wb + (size_t)(c + 512) * ld;
    const float* w2 = Wb + (size_t)(c + 1024) * ld;
    const float2* x2 = (const float2*)x;
    const float2* h2 = (const float2*)hin;

    for (int k0 = 0; k0 < HV; k0 += 128) {
        __syncthreads();
#pragma unroll
        for (int i = tid; i < 2048; i += 512) {
            int kp = i & 63, bb = i >> 6;
            float2 xv = x2[bb * 256 + (k0 >> 1) + kp];
            float2 hv = h2[bb * 256 + (k0 >> 1) + kp];
            xP[kp][bb] = *(const u64*)&xv;
            hP[kp][bb] = *(const u64*)&hv;
        }
        __syncthreads();
        const u64 (*P)[33] = sd ? hP : xP;
#pragma unroll
        for (int j = 0; j < 16; j++) {
            int kp0 = 4 * j + 2 * hf;
            float4 a4 = *(const float4*)(w0 + k0 + 2 * kp0);
            float4 b4 = *(const float4*)(w1 + k0 + 2 * kp0);
            float4 c4 = *(const float4*)(w2 + k0 + 2 * kp0);
            u64 v0 = P[kp0][lane], v1 = P[kp0 + 1][lane];
            fma2(s0, v0, ((const u64*)&a4)[0]); fma2(s0, v1, ((const u64*)&a4)[1]);
            fma2(s1, v0, ((const u64*)&b4)[0]); fma2(s1, v1, ((const u64*)&b4)[1]);
            fma2(s2, v0, ((const u64*)&c4)[0]); fma2(s2, v1, ((const u64*)&c4)[1]);
        }
    }
    cmb[w][lane][0] = s0; cmb[w][lane][1] = s1; cmb[w][lane][2] = s2;
    __syncthreads();
    if ((w & 3) == 0) {
        int b = lane;
        float xR = hsum2(cmb[w][b][0]) + hsum2(cmb[w + 1][b][0]);
        float xZ = hsum2(cmb[w][b][1]) + hsum2(cmb[w + 1][b][1]);
        float xN = hsum2(cmb[w][b][2]) + hsum2(cmb[w + 1][b][2]);
        float hR = hsum2(cmb[w + 2][b][0]) + hsum2(cmb[w + 3][b][0]);
        float hZ = hsum2(cmb[w + 2][b][1]) + hsum2(cmb[w + 3][b][1]);
        float hN = hsum2(cmb[w + 2][b][2]) + hsum2(cmb[w + 3][b][2]);
        float ir = gib[(size_t)b * gibs + c] + xR;
        float iz = gib[(size_t)b * gibs + c + 512] + xZ;
        float inn = gib[(size_t)b * gibs + c + 1024] + xN;
        float hr = hR + bhh[c], hz = hZ + bhh[c + 512], hn = hN + bhh[c + 1024];
        float r = 1.f / (1.f + expf(-(ir + hr)));
        float z = 1.f / (1.f + expf(-(iz + hz)));
        float n = tanhf(inn + r * hn);
        float hp = hin[b * HV + c];
        hout[b * HV + c] = (1.f - z) * n + z * hp;
    }
}

// ---------------- attention step: q proj + scores + softmax + context -------
__global__ __launch_bounds__(256) void attn_step(
    const float* __restrict__ h1n, const float* __restrict__ qenc,
    const float* __restrict__ encbt, const float* __restrict__ Wd,
    const float* __restrict__ bd, float* __restrict__ ctx,
    float* __restrict__ feat, int t)
{
    int b = blockIdx.x;
    __shared__ float h1s[512], qs[512], es[128], red1[8], red2[8];
    int tid = threadIdx.x, lane = tid & 31, warp = tid >> 5;
    h1s[tid] = h1n[b * 512 + tid];
    h1s[tid + 256] = h1n[b * 512 + tid + 256];
    __syncthreads();
    // q[a] = h1n[b] . Wd[a] + bd[a]
#pragma unroll 4
    for (int ai = 0; ai < 64; ai++) {
        int a = warp * 64 + ai;
        const float* w = Wd + (size_t)a * 512;
        float s = 0.f;
#pragma unroll
        for (int i = 0; i < 16; i++) s += h1s[lane + 32 * i] * w[lane + 32 * i];
#pragma unroll
        for (int o = 16; o; o >>= 1) s += __shfl_xor_sync(0xffffffffu, s, o);
        if (lane == 0) qs[a] = s + bd[a];
    }
    __syncthreads();
    // e[l] = tanh(enc_q[b][l] . q)
#pragma unroll 4
    for (int li = 0; li < 16; li++) {
        int l = warp * 16 + li;
        const float* eq = qenc + (size_t)(b * LV + l) * AV;
        float s = 0.f;
#pragma unroll
        for (int i = 0; i < 16; i++) s += qs[lane + 32 * i] * eq[lane + 32 * i];
#pragma unroll
        for (int o = 16; o; o >>= 1) s += __shfl_xor_sync(0xffffffffu, s, o);
        if (lane == 0) es[l] = tanhf(s);
    }
    __syncthreads();
    // softmax over 128
    float v = (tid < 128) ? es[tid] : -1e30f;
    float m = v;
#pragma unroll
    for (int o = 16; o; o >>= 1) m = fmaxf(m, __shfl_xor_sync(0xffffffffu, m, o));
    if (lane == 0) red1[warp] = m;
    __syncthreads();
    float mx = fmaxf(fmaxf(fmaxf(red1[0], red1[1]), fmaxf(red1[2], red1[3])),
                     fmaxf(fmaxf(red1[4], red1[5]), fmaxf(red1[6], red1[7])));
    float ex = (tid < 128) ? expf(v - mx) : 0.f;
    float s2 = ex;
#pragma unroll
    for (int o = 16; o; o >>= 1) s2 += __shfl_xor_sync(0xffffffffu, s2, o);
    if (lane == 0) red2[warp] = s2;
    __syncthreads();
    float tot = red2[0] + red2[1] + red2[2] + red2[3] + red2[4] + red2[5] + red2[6] + red2[7];
    if (tid < 128) es[tid] = ex / tot;
    __syncthreads();
    // ctx2[h] = sum_l w[l] * enc_bt[b][l][h]
    float c0 = 0.f, c1 = 0.f;
#pragma unroll 8
    for (int l = 0; l < 128; l++) {
        float w = es[l];
        const float* er = encbt + (size_t)(b * LV + l) * HV;
        c0 += w * er[tid];
        c1 += w * er[tid + 256];
    }
    ctx[b * HV + tid] = c0;
    ctx[b * HV + tid + 256] = c1;
    float* fr = feat + (size_t)(b * TDV + t) * 1024;
    fr[tid] = h1s[tid];
    fr[tid + 256] = h1s[tid + 256];
    fr[512 + tid] = c0;
    fr[512 + tid + 256] = c1;
}

// ---------------- encoder output: sum halves + transpose --------------------
__global__ void enc_combine(const float* __restrict__ y1, float* __restrict__ encbt) {
    int i = blockIdx.x * 256 + threadIdx.x;
    if (i >= BV * LV * HV) return;
    int h = i & 511; int bl = i >> 9; int b = bl >> 7; int l = bl & 127;
    size_t src = (size_t)(l * BV + b) * 1024 + h;
    encbt[i] = y1[src] + y1[src + 512];
}

// ---------------- host orchestration ----------------------------------------
extern "C" void kernel_launch(void* const* d_in, const int* in_sizes, int n_in,
                              void* d_out, int out_size) {
    const int* src = (const int*)d_in[0];
    const int* trg = (const int*)d_in[1];
    int o = (n_in >= 29 && in_sizes[2] == 1) ? 3 : 2;   // skip out_len scalar if present
    const float* enc_embed = (const float*)d_in[o + 0];
    const float* eWih0 = (const float*)d_in[o + 1];
    const float* eWhh0 = (const float*)d_in[o + 2];
    const float* ebih0 = (const float*)d_in[o + 3];
    const float* ebhh0 = (const float*)d_in[o + 4];
    const float* eWih1 = (const float*)d_in[o + 5];
    const float* eWhh1 = (const float*)d_in[o + 6];
    const float* ebih1 = (const float*)d_in[o + 7];
    const float* ebhh1 = (const float*)d_in[o + 8];
    const float* dec_embed = (const float*)d_in[o + 9];
    const float* dWih0 = (const float*)d_in[o + 10];
    const float* dWhh0 = (const float*)d_in[o + 11];
    const float* dbih0 = (const float*)d_in[o + 12];
    const float* dbhh0 = (const float*)d_in[o + 13];
    const float* dWih1 = (const float*)d_in[o + 14];
    const float* dWhh1 = (const float*)d_in[o + 15];
    const float* dbih1 = (const float*)d_in[o + 16];
    const float* dbhh1 = (const float*)d_in[o + 17];
    const float* We = (const float*)d_in[o + 18];
    const float* be = (const float*)d_in[o + 19];
    const float* Wd = (const float*)d_in[o + 20];
    const float* bd = (const float*)d_in[o + 21];
    const float* W1 = (const float*)d_in[o + 22];
    const float* b1 = (const float*)d_in[o + 23];
    const float* W2 = (const float*)d_in[o + 24];
    const float* b2 = (const float*)d_in[o + 25];
    float* out = (float*)d_out;

    float *emb, *gi0, *y0, *gi1, *y1, *encbt, *qenc, *demb, *dgi, *feat, *hid, *st;
    cudaGetSymbolAddress((void**)&emb, g_emb);
    cudaGetSymbolAddress((void**)&gi0, g_gi0);
    cudaGetSymbolAddress((void**)&y0, g_y0);
    cudaGetSymbolAddress((void**)&gi1, g_gi1);
    cudaGetSymbolAddress((void**)&y1, g_y1);
    cudaGetSymbolAddress((void**)&encbt, g_encbt);
    cudaGetSymbolAddress((void**)&qenc, g_qenc);
    cudaGetSymbolAddress((void**)&demb, g_demb);
    cudaGetSymbolAddress((void**)&dgi, g_dgi);
    cudaGetSymbolAddress((void**)&feat, g_feat);
    cudaGetSymbolAddress((void**)&hid, g_hid);
    cudaGetSymbolAddress((void**)&st, g_state);
    float* hE0 = st;                 // 4*BH
    float* hE1 = st + 4 * BH;        // 4*BH
    float* hd0 = st + 8 * BH;        // 2*BH
    float* hd1 = st + 10 * BH;       // 2*BH
    float* ctx = st + 12 * BH;       // BH

    // zero ALL recurrent state in one launch (deterministic every call)
    zero_f<<<(13 * BH + 255) / 256, 256>>>(st, 13 * BH);

    // ---------------- encoder ----------------
    gather_src<<<LV * BV, 128>>>(enc_embed, src, emb);
    for (int d = 0; d < 2; d++)
        sgemm_tn<<<dim3(32, 12), 256>>>(emb, 512, eWih0 + (size_t)d * H3V * EV, 512,
                                        ebih0 + d * H3V, gi0 + (size_t)d * LV * BV * H3V, H3V,
                                        LV * BV, 512, 0);
    for (int t = 0; t < LV; t++)
        gru_step_enc<<<dim3(128, 2), 256>>>(gi0, gi0 + (size_t)LV * BV * H3V,
                                            eWhh0, ebhh0, hE0, t & 1, y0, t, LV - 1 - t);
    for (int d = 0; d < 2; d++)
        sgemm_tn<<<dim3(32, 12), 256>>>(y0, 1024, eWih1 + (size_t)d * H3V * 1024, 1024,
                                        ebih1 + d * H3V, gi1 + (size_t)d * LV * BV * H3V, H3V,
                                        LV * BV, 1024, 0);
    for (int t = 0; t < LV; t++)
        gru_step_enc<<<dim3(128, 2), 256>>>(gi1, gi1 + (size_t)LV * BV * H3V,
                                            eWhh1, ebhh1, hE1, t & 1, y1, t, LV - 1 - t);
    enc_combine<<<(BV * LV * HV + 255) / 256, 256>>>(y1, encbt);
    sgemm_tn<<<dim3(32, 4), 256>>>(encbt, 512, We, 512, be, qenc, 512, BV * LV, 512, 0);

    // ---------------- decoder precompute ----------------
    gather_dec<<<MROWS, 128>>>(dec_embed, trg, demb);
    sgemm_tn<<<dim3(16, 12), 256>>>(demb, 512, dWih0, 1024, dbih0, dgi, H3V, MROWS, 512, 0);

    // ---------------- decode loop ----------------
    for (int t = 0; t < TDV; t++) {
        int ping = t & 1, pong = ping ^ 1;
        gru_step_dec<<<128, 512>>>(dgi + (size_t)t * BV * H3V, H3V, ctx, dWih0 + 512, 1024,
                                   hd0 + ping * BH, dWhh0, dbhh0, hd0 + pong * BH);
        gru_step_dec<<<128, 512>>>(dbih1, 0, hd0 + pong * BH, dWih1, 512,
                                   hd1 + ping * BH, dWhh1, dbhh1, hd1 + pong * BH);
        attn_step<<<BV, 256>>>(hd1 + pong * BH, qenc, encbt, Wd, bd, ctx, feat, t);
    }

    // ---------------- MLP + logits ----------------
    sgemm_tn<<<dim3(16, 8), 256>>>(feat, 1024, W1, 1024, b1, hid, 1024, MROWS, 1024, 1);
    sgemm_tn<<<dim3(16, 250), 256>>>(hid, 1024, W2, 1024, b2, out, VOC, MROWS, 1024, 0);
}